// round 13
// baseline (speedup 1.0000x reference)
#include <cuda_runtime.h>

// TensorProductUniform3x1d:
//   B=100000, NSEG=4, U=128, NPATH=20
//   out[b, i2, :] += c[p] * x0[b, i0[p], :] * x1[b, i1[p], :]
//
// FINAL (confirmed twice at dur_us=90.62): measured-best configuration
// from the full 12-round lever scan —
//   * float4 accesses (128-bit; float2 regressed ~5%)
//   * one warp per row, 8 front-batched loads (2 rows/warp: -14%)
//   * default cache policy (.cs loads -3%, .cs stores -2%, L2::256B neutral)
//   * linear CTA ordering (persistent grid-stride: -10%, DRAM locality loss)
//   * 512-thread blocks, 2 CTAs/SM (scan: 256=92.2, 512=90.6, 1024=94.3)
//   * fused per-block W build in shared memory (single launch)
// Runs the irreducible 614MB at ~6.7TB/s (84% HBM spec); residual gap is
// 2R:1W bus turnaround, not software-addressable.

#define NSEG 4
#define U 128
#define NPATH 20

__global__ __launch_bounds__(512, 2)
void tp_uniform_fused_kernel(const float4* __restrict__ x0,
                             const float4* __restrict__ x1,
                             const float*  __restrict__ coeff,
                             const int*    __restrict__ idx,
                             float4* __restrict__ out,
                             int nrows) {
    __shared__ float sW[NSEG * NSEG * NSEG];

    // Build W[i2][i0][i1] = sum_p coeff[p] * [idx[p]==(i0,i1,i2)]
    int t = threadIdx.x;
    if (t < NSEG * NSEG * NSEG) {
        int i2 = t >> 4;
        int i0 = (t >> 2) & 3;
        int i1 = t & 3;
        float w = 0.0f;
        #pragma unroll
        for (int p = 0; p < NPATH; p++) {
            int p0 = __ldg(&idx[3 * p + 0]);
            int p1 = __ldg(&idx[3 * p + 1]);
            int p2 = __ldg(&idx[3 * p + 2]);
            if (p0 == i0 && p1 == i1 && p2 == i2) w += __ldg(&coeff[p]);
        }
        sW[t] = w;
    }
    __syncthreads();

    int gid  = blockIdx.x * blockDim.x + threadIdx.x;
    int row  = gid >> 5;
    int lane = gid & 31;
    if (row >= nrows) return;

    size_t base = (size_t)row * (NSEG * U / 4) + lane;  // float4 units

    // Front-batch all 8 loads (default cache policy — measured best).
    float4 a[NSEG], b[NSEG];
    #pragma unroll
    for (int s = 0; s < NSEG; s++) a[s] = __ldg(&x0[base + s * (U / 4)]);
    #pragma unroll
    for (int s = 0; s < NSEG; s++) b[s] = __ldg(&x1[base + s * (U / 4)]);

    // out[i2] = sum_{i0} a[i0] * ( sum_{i1} W[i2][i0][i1] * b[i1] )
    #pragma unroll
    for (int i2 = 0; i2 < NSEG; i2++) {
        float4 acc = make_float4(0.f, 0.f, 0.f, 0.f);
        #pragma unroll
        for (int i0 = 0; i0 < NSEG; i0++) {
            float4 tt = make_float4(0.f, 0.f, 0.f, 0.f);
            #pragma unroll
            for (int i1 = 0; i1 < NSEG; i1++) {
                float w = sW[(i2 * NSEG + i0) * NSEG + i1];
                tt.x = fmaf(w, b[i1].x, tt.x);
                tt.y = fmaf(w, b[i1].y, tt.y);
                tt.z = fmaf(w, b[i1].z, tt.z);
                tt.w = fmaf(w, b[i1].w, tt.w);
            }
            acc.x = fmaf(a[i0].x, tt.x, acc.x);
            acc.y = fmaf(a[i0].y, tt.y, acc.y);
            acc.z = fmaf(a[i0].z, tt.z, acc.z);
            acc.w = fmaf(a[i0].w, tt.w, acc.w);
        }
        out[base + i2 * (U / 4)] = acc;
    }
}

extern "C" void kernel_launch(void* const* d_in, const int* in_sizes, int n_in,
                              void* d_out, int out_size) {
    const float4* x0    = (const float4*)d_in[0];
    const float4* x1    = (const float4*)d_in[1];
    const float*  coeff = (const float*)d_in[2];
    const int*    idx   = (const int*)d_in[3];
    float4*       out   = (float4*)d_out;

    int nrows = in_sizes[0] / (NSEG * U);   // 100000

    int total_threads = nrows * 32;         // one warp per row
    int block = 512;
    int grid  = (total_threads + block - 1) / block;
    tp_uniform_fused_kernel<<<grid, block>>>(x0, x1, coeff, idx, out, nrows);
}

// round 14
// speedup vs baseline: 1.0021x; 1.0021x over previous
#include <cuda_runtime.h>

// TensorProductUniform3x1d:
//   B=100000, NSEG=4, U=128, NPATH=20
//   out[b, i2, :] += c[p] * x0[b, i0[p], :] * x1[b, i1[p], :]
//
// FINAL (best measured: dur_us 90.62 twice, 91.4 once; mean ~90.9):
//   * float4 accesses (128-bit; float2 regressed ~5%)
//   * one warp per row, 8 front-batched loads (2 rows/warp: -14%)
//   * default cache policy (.cs loads -3%, .cs stores -2%, L2::256B neutral)
//   * linear CTA ordering (persistent grid-stride: -10%, DRAM locality loss)
//   * 512-thread blocks, 2 CTAs/SM (scan: 256=92.2, 512=90.6, 1024=94.3)
//   * fused per-block W build in shared memory (single launch)
// Moves the irreducible 614MB at ~6.7TB/s (84% HBM spec). Residual gap is
// 2R:1W bus turnaround — path-independent per the B300 model, so no
// software restructuring (TMA stores, smem staging) can recover it.

#define NSEG 4
#define U 128
#define NPATH 20

__global__ __launch_bounds__(512, 2)
void tp_uniform_fused_kernel(const float4* __restrict__ x0,
                             const float4* __restrict__ x1,
                             const float*  __restrict__ coeff,
                             const int*    __restrict__ idx,
                             float4* __restrict__ out,
                             int nrows) {
    __shared__ float sW[NSEG * NSEG * NSEG];

    // Build W[i2][i0][i1] = sum_p coeff[p] * [idx[p]==(i0,i1,i2)]
    int t = threadIdx.x;
    if (t < NSEG * NSEG * NSEG) {
        int i2 = t >> 4;
        int i0 = (t >> 2) & 3;
        int i1 = t & 3;
        float w = 0.0f;
        #pragma unroll
        for (int p = 0; p < NPATH; p++) {
            int p0 = __ldg(&idx[3 * p + 0]);
            int p1 = __ldg(&idx[3 * p + 1]);
            int p2 = __ldg(&idx[3 * p + 2]);
            if (p0 == i0 && p1 == i1 && p2 == i2) w += __ldg(&coeff[p]);
        }
        sW[t] = w;
    }
    __syncthreads();

    int gid  = blockIdx.x * blockDim.x + threadIdx.x;
    int row  = gid >> 5;
    int lane = gid & 31;
    if (row >= nrows) return;

    size_t base = (size_t)row * (NSEG * U / 4) + lane;  // float4 units

    // Front-batch all 8 loads (default cache policy — measured best).
    float4 a[NSEG], b[NSEG];
    #pragma unroll
    for (int s = 0; s < NSEG; s++) a[s] = __ldg(&x0[base + s * (U / 4)]);
    #pragma unroll
    for (int s = 0; s < NSEG; s++) b[s] = __ldg(&x1[base + s * (U / 4)]);

    // out[i2] = sum_{i0} a[i0] * ( sum_{i1} W[i2][i0][i1] * b[i1] )
    #pragma unroll
    for (int i2 = 0; i2 < NSEG; i2++) {
        float4 acc = make_float4(0.f, 0.f, 0.f, 0.f);
        #pragma unroll
        for (int i0 = 0; i0 < NSEG; i0++) {
            float4 tt = make_float4(0.f, 0.f, 0.f, 0.f);
            #pragma unroll
            for (int i1 = 0; i1 < NSEG; i1++) {
                float w = sW[(i2 * NSEG + i0) * NSEG + i1];
                tt.x = fmaf(w, b[i1].x, tt.x);
                tt.y = fmaf(w, b[i1].y, tt.y);
                tt.z = fmaf(w, b[i1].z, tt.z);
                tt.w = fmaf(w, b[i1].w, tt.w);
            }
            acc.x = fmaf(a[i0].x, tt.x, acc.x);
            acc.y = fmaf(a[i0].y, tt.y, acc.y);
            acc.z = fmaf(a[i0].z, tt.z, acc.z);
            acc.w = fmaf(a[i0].w, tt.w, acc.w);
        }
        out[base + i2 * (U / 4)] = acc;
    }
}

extern "C" void kernel_launch(void* const* d_in, const int* in_sizes, int n_in,
                              void* d_out, int out_size) {
    const float4* x0    = (const float4*)d_in[0];
    const float4* x1    = (const float4*)d_in[1];
    const float*  coeff = (const float*)d_in[2];
    const int*    idx   = (const int*)d_in[3];
    float4*       out   = (float4*)d_out;

    int nrows = in_sizes[0] / (NSEG * U);   // 100000

    int total_threads = nrows * 32;         // one warp per row
    int block = 512;
    int grid  = (total_threads + block - 1) / block;
    tp_uniform_fused_kernel<<<grid, block>>>(x0, x1, coeff, idx, out, nrows);
}